// round 16
// baseline (speedup 1.0000x reference)
#include <cuda_runtime.h>
#include <cuda_fp16.h>
#include <cstdint>
#include <cstddef>

#define B_     64
#define T_     512
#define D_     1024
#define U_     1024
#define G_     4128
#define NUB_   128          // unit blocks
#define NB_    129          // + 1 master block

// ---------------- static device scratch (no allocation APIs) ----------------
__device__ __align__(256) uint4 g_xtq[(size_t)T_ * 8192]; // x A-frag quads, per-step
__device__ __align__(256) uint4 g_bq[(size_t)NB_ * 8192]; // [W;R] B-frag quads per block
__device__ __align__(256) uint4 g_hq[2][8192];            // h A-frag quads, ping-pong
__device__ __align__(256) float g_masters[B_ * 32];
__device__ unsigned g_ctr;
__device__ unsigned g_mflag;

// ---------------- helpers ----------------------------------------------------
__device__ __forceinline__ unsigned pack2(float lo, float hi) {
    __half2 h = __floats2half2_rn(lo, hi);
    return *reinterpret_cast<unsigned*>(&h);
}
__device__ __forceinline__ void mma_f16(float c[4], unsigned a0, unsigned a1,
                                        unsigned a2, unsigned a3,
                                        unsigned b0, unsigned b1) {
    asm volatile(
        "mma.sync.aligned.m16n8k16.row.col.f32.f16.f16.f32 "
        "{%0,%1,%2,%3},{%4,%5,%6,%7},{%8,%9},{%0,%1,%2,%3};"
        : "+f"(c[0]), "+f"(c[1]), "+f"(c[2]), "+f"(c[3])
        : "r"(a0), "r"(a1), "r"(a2), "r"(a3), "r"(b0), "r"(b1));
}
__device__ __forceinline__ void cp16(void* s, const void* g) {
    unsigned a = (unsigned)__cvta_generic_to_shared(s);
    asm volatile("cp.async.cg.shared.global [%0], [%1], 16;" :: "r"(a), "l"(g));
}
__device__ __forceinline__ void cpcommit() { asm volatile("cp.async.commit_group;"); }
template<int N> __device__ __forceinline__ void cpwait() {
    asm volatile("cp.async.wait_group %0;" :: "n"(N));
}
#define BSYNC(id, cnt)  asm volatile("bar.sync "  #id ", " #cnt ";" ::: "memory")
#define BARR(id, cnt)   asm volatile("bar.arrive " #id ", " #cnt ";" ::: "memory")

// ---------------- prepack kernels (layouts identical to R15) ------------------
__global__ void k_pack_aq(const float* __restrict__ x) {
    size_t qid = (size_t)blockIdx.x * 256 + threadIdx.x;
    if (qid >= (size_t)T_ * 8192) return;
    int t    = (int)(qid >> 13);
    int rem  = (int)(qid & 8191);
    int ku   = rem >> 7;
    int mgrp = (rem >> 5) & 3;
    int lane = rem & 31;
    int grp = lane >> 2, tig = lane & 3;
    int b0 = mgrp * 16 + grp;
    int k0 = ku * 16 + 2 * tig;
    const float* x0 = x + ((size_t)b0 * T_ + t) * D_;
    const float* x1 = x + ((size_t)(b0 + 8) * T_ + t) * D_;
    uint4 q;
    q.x = pack2(x0[k0],     x0[k0 + 1]);
    q.y = pack2(x1[k0],     x1[k0 + 1]);
    q.z = pack2(x0[k0 + 8], x0[k0 + 9]);
    q.w = pack2(x1[k0 + 8], x1[k0 + 9]);
    g_xtq[qid] = q;
}

__global__ void k_pack_bq(const float* __restrict__ W, const float* __restrict__ R) {
    int qid = blockIdx.x * 256 + threadIdx.x;
    if (qid >= NB_ * 8192) return;
    int bk  = qid >> 13;
    int rem = qid & 8191;
    int ku2 = rem >> 7;
    int col = (rem >> 2) & 31;
    int tig = rem & 3;
    int sc = (bk == NUB_) ? col : 32 + (col >> 3) * 1024 + bk * 8 + (col & 7);
    const float* M = (ku2 < 32) ? W : R;
    int kb = (ku2 & 31) * 32 + 2 * tig;
    const float* Mc = M + sc;
    uint4 q;
    q.x = pack2(Mc[(size_t)(kb)      * G_], Mc[(size_t)(kb + 1)  * G_]);
    q.y = pack2(Mc[(size_t)(kb + 8)  * G_], Mc[(size_t)(kb + 9)  * G_]);
    q.z = pack2(Mc[(size_t)(kb + 16) * G_], Mc[(size_t)(kb + 17) * G_]);
    q.w = pack2(Mc[(size_t)(kb + 24) * G_], Mc[(size_t)(kb + 25) * G_]);
    g_bq[qid] = q;
}

__global__ void k_zero() {
    int i = blockIdx.x * blockDim.x + threadIdx.x;
    if (i < 8192) g_hq[0][i] = make_uint4(0u, 0u, 0u, 0u);
    if (i == 0) { g_ctr = 0u; g_mflag = 0u; }
}

// ---------------- K=512 register-streamed GEMM (m32 x n32) --------------------
// asrc: A quad block base (8192 quads); kub: k16 base; b2base: B k32 base.
__device__ __forceinline__ void gemm_k512(const uint4* __restrict__ asrc, int kub,
                                          int b2base, const uint4* Bs,
                                          int tile, int lane, int grp, int tig,
                                          float acc[2][4][4]) {
    uint4 buf[3][8];
    const uint4* abase = asrc + (size_t)kub * 128 + (tile * 2) * 32 + lane;
    #pragma unroll
    for (int pre = 0; pre < 2; pre++) {
        const uint4* p = abase + pre * 4 * 128;
        #pragma unroll
        for (int i = 0; i < 4; i++)
            #pragma unroll
            for (int mt = 0; mt < 2; mt++)
                buf[pre][i * 2 + mt] = __ldcg(p + i * 128 + mt * 32);
    }
    #pragma unroll
    for (int sc = 0; sc < 8; sc++) {
        if (sc < 6) {
            const uint4* p = abase + (sc + 2) * 4 * 128;
            uint4* dst = buf[(sc + 2) % 3];
            #pragma unroll
            for (int i = 0; i < 4; i++)
                #pragma unroll
                for (int mt = 0; mt < 2; mt++)
                    dst[i * 2 + mt] = __ldcg(p + i * 128 + mt * 32);
        }
        const uint4* cur = buf[sc % 3];
        #pragma unroll
        for (int j = 0; j < 2; j++) {
            int ku2g = b2base + sc * 2 + j;
            uint4 bq[4];
            #pragma unroll
            for (int nt = 0; nt < 4; nt++)
                bq[nt] = Bs[ku2g * 128 + nt * 32 + lane];
            #pragma unroll
            for (int mt = 0; mt < 2; mt++) {
                uint4 aE = cur[(2 * j) * 2 + mt];
                uint4 aO = cur[(2 * j + 1) * 2 + mt];
                #pragma unroll
                for (int nt = 0; nt < 4; nt++) {
                    mma_f16(acc[mt][nt], aE.x, aE.y, aE.z, aE.w, bq[nt].x, bq[nt].y);
                    mma_f16(acc[mt][nt], aO.x, aO.y, aO.z, aO.w, bq[nt].z, bq[nt].w);
                }
            }
        }
    }
}

// ---------------- fused persistent kernel (warp-specialized) ------------------
// warps 0-3: x-producers (step t+1). warps 4-7: h-consumers (critical path).
// smem: Bs 8192u4 (128KB) | redX [2][2][2][256]f4 (32KB) | redH [2][256]f4 (8KB)
//       | zs 64x33f (8.25KB, master only) | bs 32f
__global__ __launch_bounds__(256, 1) void k_rec(float* __restrict__ out,
                                                const float* __restrict__ bias) {
    extern __shared__ uint4 sm4[];
    uint4*  Bs    = sm4;                           // 8192
    float4* redX4 = (float4*)(sm4 + 8192);         // 2048
    float4* redH4 = redX4 + 2048;                  // 512
    float*  zs    = (float*)(redH4 + 512);         // 64*33
    float*  bs    = zs + 64 * 33;                  // 32

    const int tid  = threadIdx.x;
    const int bk   = blockIdx.x;
    const int warp = tid >> 5, lane = tid & 31;
    const int grp  = lane >> 2, tig = lane & 3;
    const bool hrole = (warp >= 4);
    const int rw   = hrole ? (warp - 4) : warp;
    const int tile = rw & 1;
    const int kseg = rw >> 1;
    const bool master = (bk == NUB_);

    // one-time init
    {
        const uint4* bsrc = g_bq + (size_t)bk * 8192;
        #pragma unroll
        for (int r = 0; r < 32; r++) cp16(Bs + tid + r * 256, bsrc + tid + r * 256);
        cpcommit(); cpwait<0>();
        if (tid < 32) {
            int sc = master ? tid : 32 + (tid >> 3) * 1024 + bk * 8 + (tid & 7);
            bs[tid] = bias[sc];
        }
        __syncthreads();
    }

    if (!hrole) {
        // ---------------- x-producer warps ----------------
        for (int s = 0; s < T_; s++) {
            float acc[2][4][4];
            #pragma unroll
            for (int a = 0; a < 2; a++)
                #pragma unroll
                for (int b = 0; b < 4; b++)
                    #pragma unroll
                    for (int c = 0; c < 4; c++) acc[a][b][c] = 0.f;
            gemm_k512(g_xtq + (size_t)s * 8192, 32 * kseg, 16 * kseg,
                      Bs, tile, lane, grp, tig, acc);
            if (s > 0) BSYNC(2, 256);       // wait: slot consumed (depth-1 ahead)
            float4* dst = redX4 + (s & 1) * 1024 + kseg * 512 + tile * 256 + lane * 8;
            #pragma unroll
            for (int q = 0; q < 8; q++) {
                int mt = q >> 2, nt = q & 3;
                dst[q] = make_float4(acc[mt][nt][0], acc[mt][nt][1],
                                     acc[mt][nt][2], acc[mt][nt][3]);
            }
            BARR(1, 256);                   // publish redX(s)
        }
    } else {
        // ---------------- h-consumer warps (critical path) ----------------
        const int u0  = bk * 8;
        const int lvl = bk >> 3;
        const int htid = tid - 128;         // 0..127
        float creg[8] = {0.f,0.f,0.f,0.f,0.f,0.f,0.f,0.f};

        for (int t = 0; t < T_; ++t) {
            if (lane == 0) {
                unsigned tgt = 129u * (unsigned)t;
                while (*(volatile unsigned*)&g_ctr < tgt) __nanosleep(32);
            }
            __syncwarp();

            float acc[2][4][4];
            #pragma unroll
            for (int a = 0; a < 2; a++)
                #pragma unroll
                for (int b = 0; b < 4; b++)
                    #pragma unroll
                    for (int c = 0; c < 4; c++) acc[a][b][c] = 0.f;
            gemm_k512(g_hq[t & 1], 32 * kseg, 32 + 16 * kseg,
                      Bs, tile, lane, grp, tig, acc);

            if (kseg == 1) {
                float4* dst = redH4 + tile * 256 + lane * 8;
                #pragma unroll
                for (int q = 0; q < 8; q++) {
                    int mt = q >> 2, nt = q & 3;
                    dst[q] = make_float4(acc[mt][nt][0], acc[mt][nt][1],
                                         acc[mt][nt][2], acc[mt][nt][3]);
                }
            }
            BSYNC(3, 128);                       // h reads done + redH ready
            if (master && htid == 0) atomicAdd(&g_ctr, 1u);   // early arrive
            BSYNC(1, 256);                       // redX(t) published

            if (kseg == 0) {
                const float4* pX0 = redX4 + (t & 1) * 1024 + tile * 256 + lane * 8;
                const float4* pX1 = pX0 + 512;
                const float4* pH  = redH4 + tile * 256 + lane * 8;
                #pragma unroll
                for (int q = 0; q < 8; q++) {
                    int mt = q >> 2, nt = q & 3;
                    float4 a = pX0[q], b4 = pX1[q], c4 = pH[q];
                    acc[mt][nt][0] += a.x + b4.x + c4.x;
                    acc[mt][nt][1] += a.y + b4.y + c4.y;
                    acc[mt][nt][2] += a.z + b4.z + c4.z;
                    acc[mt][nt][3] += a.w + b4.w + c4.w;
                }
                #pragma unroll
                for (int nt = 0; nt < 4; nt++) {
                    float b0 = bs[nt * 8 + tig * 2], b1 = bs[nt * 8 + tig * 2 + 1];
                    #pragma unroll
                    for (int mt = 0; mt < 2; mt++) {
                        acc[mt][nt][0] += b0; acc[mt][nt][1] += b1;
                        acc[mt][nt][2] += b0; acc[mt][nt][3] += b1;
                    }
                }
            }
            if (t < T_ - 1) BARR(2, 256);        // redX slot consumed

            if (master) {
                if (kseg == 0) {
                    #pragma unroll
                    for (int mt = 0; mt < 2; mt++) {
                        int r0 = tile * 32 + mt * 16 + grp;
                        #pragma unroll
                        for (int nt = 0; nt < 4; nt++) {
                            int c0 = nt * 8 + tig * 2;
                            zs[r0 * 33 + c0]           = acc[mt][nt][0];
                            zs[r0 * 33 + c0 + 1]       = acc[mt][nt][1];
                            zs[(r0 + 8) * 33 + c0]     = acc[mt][nt][2];
                            zs[(r0 + 8) * 33 + c0 + 1] = acc[mt][nt][3];
                        }
                    }
                }
                BSYNC(3, 128);
                {
                    int b = htid >> 1, half = htid & 1;
                    const float* lz = zs + b * 33 + half * 16;
                    float v[16], mx = -1e30f;
                    #pragma unroll
                    for (int i = 0; i < 16; i++) { v[i] = lz[i]; mx = fmaxf(mx, v[i]); }
                    float s = 0.f;
                    #pragma unroll
                    for (int i = 0; i < 16; i++) { v[i] = expf(v[i] - mx); s += v[i]; }
                    float inv = 1.f / s;
                    if (half == 0) {
                        float run = 0.f;
                        #pragma unroll
                        for (int i = 0; i < 16; i++) {
                            run += v[i] * inv;
                            __stcg(&g_masters[b * 32 + i], run);
                        }
                    } else {
                        float run = 0.f;
                        #pragma unroll
                        for (int i = 15; i >= 0; i--) {
                            run += v[i] * inv;
                            __stcg(&g_masters[b * 32 + 16 + i], run);
                        }
                    }
                }
                __threadfence();
                BSYNC(3, 128);
                if (htid == 0) *(volatile unsigned*)&g_mflag = (unsigned)(t + 1);
            } else {
                if (kseg == 0) {
                    // gates from register z (cix = mt*4 + dr*2 + dj)
                    float pf[8], pi[8], po[8], pg[8];
                    #pragma unroll
                    for (int mt = 0; mt < 2; mt++)
                        #pragma unroll
                        for (int e = 0; e < 4; e++) {
                            int cix = mt * 4 + e;
                            pf[cix] = 1.f / (1.f + expf(-acc[mt][0][e]));
                            pi[cix] = 1.f / (1.f + expf(-acc[mt][1][e]));
                            po[cix] = 1.f / (1.f + expf(-acc[mt][2][e]));
                            pg[cix] = tanhf(acc[mt][3][e]);
                        }
                    if (lane == 0) {
                        while (*(volatile unsigned*)&g_mflag < (unsigned)(t + 1)) __nanosleep(16);
                    }
                    __syncwarp();
                    uint4* hout4 = g_hq[(t + 1) & 1];
                    int j0 = 2 * tig;
                    #pragma unroll
                    for (int mt = 0; mt < 2; mt++) {
                        int r0 = tile * 32 + mt * 16 + grp;
                        float fm0 = __ldcg(&g_masters[r0 * 32 + lvl]);
                        float im0 = __ldcg(&g_masters[r0 * 32 + 16 + lvl]);
                        float fm1 = __ldcg(&g_masters[(r0 + 8) * 32 + lvl]);
                        float im1 = __ldcg(&g_masters[(r0 + 8) * 32 + 16 + lvl]);
                        float hv[4];
                        #pragma unroll
                        for (int e = 0; e < 4; e++) {
                            int cix = mt * 4 + e;
                            float fm = (e >> 1) ? fm1 : fm0;
                            float im = (e >> 1) ? im1 : im0;
                            float w = fm * im;
                            float c = w * (pf[cix] * creg[cix] + pi[cix] * pg[cix])
                                    + (fm - w) * creg[cix] + (im - w) * pg[cix];
                            creg[cix] = c;
                            hv[e] = po[cix] * tanhf(c);
                        }
                        float2 o0 = make_float2(hv[0], hv[1]);
                        float2 o1 = make_float2(hv[2], hv[3]);
                        *(float2*)&out[((size_t)r0 * T_ + t) * U_ + u0 + j0] = o0;
                        *(float2*)&out[((size_t)(r0 + 8) * T_ + t) * U_ + u0 + j0] = o1;
                        unsigned w0 = pack2(hv[0], hv[1]);
                        unsigned w1 = pack2(hv[2], hv[3]);
                        char* dst = (char*)(hout4 + (bk >> 1) * 128
                                            + (tile * 2 + mt) * 32 + lane) + (bk & 1) * 8;
                        asm volatile("st.global.cg.v2.u32 [%0], {%1,%2};"
                                     :: "l"(dst), "r"(w0), "r"(w1) : "memory");
                    }
                    __threadfence();
                }
                BSYNC(3, 128);
                if (htid == 0) atomicAdd(&g_ctr, 1u);
            }
        }
    }
}

// ---------------- entry -------------------------------------------------------
extern "C" void kernel_launch(void* const* d_in, const int* in_sizes, int n_in,
                              void* d_out, int out_size) {
    const float* x    = (const float*)d_in[0];
    const float* W    = (const float*)d_in[1];
    const float* R    = (const float*)d_in[2];
    const float* bias = (const float*)d_in[3];
    float* out = (float*)d_out;

    // smem: 131072 + 32768 + 8192 + 8448 + 128 = 180608
    cudaFuncSetAttribute(k_rec, cudaFuncAttributeMaxDynamicSharedMemorySize, 180608);

    k_pack_aq<<<(int)(((size_t)T_ * 8192 + 255) / 256), 256>>>(x);
    k_pack_bq<<<(NB_ * 8192 + 255) / 256, 256>>>(W, R);
    k_zero<<<32, 256>>>();
    k_rec<<<NB_, 256, 180608>>>(out, bias);
}

// round 17
// speedup vs baseline: 1.1173x; 1.1173x over previous
#include <cuda_runtime.h>
#include <cuda_fp16.h>
#include <cstdint>
#include <cstddef>

#define B_     64
#define T_     512
#define D_     1024
#define U_     1024
#define G_     4128
#define NUB_   128          // unit blocks
#define NB_    129          // + 1 master block

// ---------------- static device scratch (no allocation APIs) ----------------
__device__ __align__(256) uint4 g_xtq[(size_t)T_ * 8192]; // x A-frag quads, per-step
__device__ __align__(256) uint4 g_bq[(size_t)NB_ * 8192]; // [W;R] B-frag quads per block
__device__ __align__(256) uint4 g_hq[2][8192];            // h A-frag quads, ping-pong
__device__ __align__(256) float g_masters[B_ * 32];
__device__ unsigned g_ctr;
__device__ unsigned g_mflag;

// ---------------- helpers ----------------------------------------------------
__device__ __forceinline__ unsigned pack2(float lo, float hi) {
    __half2 h = __floats2half2_rn(lo, hi);
    return *reinterpret_cast<unsigned*>(&h);
}
__device__ __forceinline__ void mma_f16(float c[4], unsigned a0, unsigned a1,
                                        unsigned a2, unsigned a3,
                                        unsigned b0, unsigned b1) {
    asm volatile(
        "mma.sync.aligned.m16n8k16.row.col.f32.f16.f16.f32 "
        "{%0,%1,%2,%3},{%4,%5,%6,%7},{%8,%9},{%0,%1,%2,%3};"
        : "+f"(c[0]), "+f"(c[1]), "+f"(c[2]), "+f"(c[3])
        : "r"(a0), "r"(a1), "r"(a2), "r"(a3), "r"(b0), "r"(b1));
}
__device__ __forceinline__ void cp16(void* s, const void* g) {
    unsigned a = (unsigned)__cvta_generic_to_shared(s);
    asm volatile("cp.async.cg.shared.global [%0], [%1], 16;" :: "r"(a), "l"(g));
}
__device__ __forceinline__ void cpcommit() { asm volatile("cp.async.commit_group;"); }
template<int N> __device__ __forceinline__ void cpwait() {
    asm volatile("cp.async.wait_group %0;" :: "n"(N));
}

// ---------------- prepack kernels (layouts identical to R15) ------------------
__global__ void k_pack_aq(const float* __restrict__ x) {
    size_t qid = (size_t)blockIdx.x * 256 + threadIdx.x;
    if (qid >= (size_t)T_ * 8192) return;
    int t    = (int)(qid >> 13);
    int rem  = (int)(qid & 8191);
    int ku   = rem >> 7;
    int mgrp = (rem >> 5) & 3;
    int lane = rem & 31;
    int grp = lane >> 2, tig = lane & 3;
    int b0 = mgrp * 16 + grp;
    int k0 = ku * 16 + 2 * tig;
    const float* x0 = x + ((size_t)b0 * T_ + t) * D_;
    const float* x1 = x + ((size_t)(b0 + 8) * T_ + t) * D_;
    uint4 q;
    q.x = pack2(x0[k0],     x0[k0 + 1]);
    q.y = pack2(x1[k0],     x1[k0 + 1]);
    q.z = pack2(x0[k0 + 8], x0[k0 + 9]);
    q.w = pack2(x1[k0 + 8], x1[k0 + 9]);
    g_xtq[qid] = q;
}

__global__ void k_pack_bq(const float* __restrict__ W, const float* __restrict__ R) {
    int qid = blockIdx.x * 256 + threadIdx.x;
    if (qid >= NB_ * 8192) return;
    int bk  = qid >> 13;
    int rem = qid & 8191;
    int ku2 = rem >> 7;
    int col = (rem >> 2) & 31;
    int tig = rem & 3;
    int sc = (bk == NUB_) ? col : 32 + (col >> 3) * 1024 + bk * 8 + (col & 7);
    const float* M = (ku2 < 32) ? W : R;
    int kb = (ku2 & 31) * 32 + 2 * tig;
    const float* Mc = M + sc;
    uint4 q;
    q.x = pack2(Mc[(size_t)(kb)      * G_], Mc[(size_t)(kb + 1)  * G_]);
    q.y = pack2(Mc[(size_t)(kb + 8)  * G_], Mc[(size_t)(kb + 9)  * G_]);
    q.z = pack2(Mc[(size_t)(kb + 16) * G_], Mc[(size_t)(kb + 17) * G_]);
    q.w = pack2(Mc[(size_t)(kb + 24) * G_], Mc[(size_t)(kb + 25) * G_]);
    g_bq[qid] = q;
}

__global__ void k_zero() {
    int i = blockIdx.x * blockDim.x + threadIdx.x;
    if (i < 8192) g_hq[0][i] = make_uint4(0u, 0u, 0u, 0u);
    if (i == 0) { g_ctr = 0u; g_mflag = 0u; }
}

// ---------------- fused persistent kernel -------------------------------------
// 129 blocks x 256 threads. z_t = [x_t, h_{t-1}] @ [W;R] + bias, K=2048.
// A streamed global->registers; B smem-resident. 2 m32n32 tiles x 4-way K-split.
// Single-wave reduction into kseg0 registers; unit epilogue entirely in regs.
// smem: Bs 8192u4 (128KB) | red 1536 f4 (24KB) | zs 64x33 (8.25KB, master) |
//       cs 512f | bs 32f
__global__ __launch_bounds__(256, 1) void k_rec(float* __restrict__ out,
                                                const float* __restrict__ bias) {
    extern __shared__ uint4 sm4[];
    uint4*  Bs   = sm4;                          // 8192
    float4* red4 = (float4*)(sm4 + 8192);        // 1536
    float*  zs   = (float*)(red4 + 1536);        // 64*33 (master only)
    float*  cs   = zs + 64 * 33;                 // 512 cell state
    float*  bs   = cs + 512;                     // 32

    const int tid  = threadIdx.x;
    const int bk   = blockIdx.x;
    const int warp = tid >> 5, lane = tid & 31;
    const int grp  = lane >> 2, tig = lane & 3;
    const int tile = warp & 1;                   // m-half: rows tile*32..+31
    const int ks   = warp >> 1;                  // k-group 0..3
    const int u0   = bk * 8;
    const int lvl  = bk >> 3;
    const bool master = (bk == NUB_);

    // per-warp A base offset within a chunk
    const int aoff0 = (ks * 2 * 2) * 128 + (tile * 2) * 32 + lane;

    // one-time: [W;R] frags -> smem, bias, zero cell state
    {
        const uint4* bsrc = g_bq + (size_t)bk * 8192;
        #pragma unroll
        for (int r = 0; r < 32; r++) cp16(Bs + tid + r * 256, bsrc + tid + r * 256);
        cpcommit(); cpwait<0>();
        if (tid < 32) {
            int sc = master ? tid : 32 + (tid >> 3) * 1024 + bk * 8 + (tid & 7);
            bs[tid] = bias[sc];
        }
        for (int i = tid; i < 512; i += 256) cs[i] = 0.f;
        __syncthreads();
    }

    uint4 areg0[8], areg1[8];
    auto issue8 = [&](const uint4* cb, uint4* dst) {
        #pragma unroll
        for (int kk = 0; kk < 2; kk++)
            #pragma unroll
            for (int par = 0; par < 2; par++)
                #pragma unroll
                for (int mt = 0; mt < 2; mt++)
                    dst[kk * 4 + par * 2 + mt] =
                        __ldcg(cb + aoff0 + (kk * 2 + par) * 128 + mt * 32);
    };

    issue8(g_xtq, areg0);   // bootstrap chunk 0 of t=0

    for (int t = 0; t < T_; ++t) {
        const uint4* xcur = g_xtq + (size_t)t * 8192;
        const uint4* xnxt = xcur + 8192;
        const uint4* hsrc = g_hq[t & 1];

        float acc[2][4][4];
        #pragma unroll
        for (int a = 0; a < 2; a++)
            #pragma unroll
            for (int b = 0; b < 4; b++)
                #pragma unroll
                for (int c = 0; c < 4; c++) acc[a][b][c] = 0.f;

        #pragma unroll
        for (int c = 0; c < 8; ++c) {
            uint4* cur = (c & 1) ? areg1 : areg0;
            uint4* nxt = (c & 1) ? areg0 : areg1;

            if (c == 3) {                      // h-ready gate (per-warp)
                if (lane == 0) {
                    unsigned target = 129u * (unsigned)t;
                    while (*(volatile unsigned*)&g_ctr < target) __nanosleep(64);
                }
                __syncwarp();
            }
            if (c < 3)      issue8(xcur + (c + 1) * 2048, nxt);
            else if (c < 7) issue8(hsrc + (c - 3) * 2048, nxt);
            else if (t + 1 < T_) issue8(xnxt, nxt);

            #pragma unroll
            for (int kk = 0; kk < 2; ++kk) {
                int ku2 = c * 8 + ks * 2 + kk;
                uint4 bq0 = Bs[ku2 * 128 + 0 * 32 + lane];
                uint4 bq1 = Bs[ku2 * 128 + 1 * 32 + lane];
                uint4 bq2 = Bs[ku2 * 128 + 2 * 32 + lane];
                uint4 bq3 = Bs[ku2 * 128 + 3 * 32 + lane];
                #pragma unroll
                for (int mt = 0; mt < 2; ++mt) {
                    uint4 aE = cur[kk * 4 + 0 * 2 + mt];
                    uint4 aO = cur[kk * 4 + 1 * 2 + mt];
                    mma_f16(acc[mt][0], aE.x, aE.y, aE.z, aE.w, bq0.x, bq0.y);
                    mma_f16(acc[mt][0], aO.x, aO.y, aO.z, aO.w, bq0.z, bq0.w);
                    mma_f16(acc[mt][1], aE.x, aE.y, aE.z, aE.w, bq1.x, bq1.y);
                    mma_f16(acc[mt][1], aO.x, aO.y, aO.z, aO.w, bq1.z, bq1.w);
                    mma_f16(acc[mt][2], aE.x, aE.y, aE.z, aE.w, bq2.x, bq2.y);
                    mma_f16(acc[mt][2], aO.x, aO.y, aO.z, aO.w, bq2.z, bq2.w);
                    mma_f16(acc[mt][3], aE.x, aE.y, aE.z, aE.w, bq3.x, bq3.y);
                    mma_f16(acc[mt][3], aO.x, aO.y, aO.z, aO.w, bq3.z, bq3.w);
                }
            }
        }

        // master: h reads complete -> arrive on ctr early
        if (master && tid == 0) atomicAdd(&g_ctr, 1u);

        // ---- single-wave reduction: ksegs 1..3 publish, kseg0 accumulates ----
        if (ks > 0) {
            float4* dst = red4 + (ks - 1) * 512 + tile * 256 + lane * 8;
            #pragma unroll
            for (int q = 0; q < 8; q++) {
                int mt = q >> 2, nt = q & 3;
                dst[q] = make_float4(acc[mt][nt][0], acc[mt][nt][1],
                                     acc[mt][nt][2], acc[mt][nt][3]);
            }
        }
        __syncthreads();   // (A) partials published
        if (ks == 0) {
            #pragma unroll
            for (int s = 0; s < 3; s++) {
                const float4* p = red4 + s * 512 + tile * 256 + lane * 8;
                #pragma unroll
                for (int q = 0; q < 8; q++) {
                    int mt = q >> 2, nt = q & 3;
                    float4 v = p[q];
                    acc[mt][nt][0] += v.x; acc[mt][nt][1] += v.y;
                    acc[mt][nt][2] += v.z; acc[mt][nt][3] += v.w;
                }
            }
            #pragma unroll
            for (int nt = 0; nt < 4; nt++) {
                float b0 = bs[nt * 8 + tig * 2], b1 = bs[nt * 8 + tig * 2 + 1];
                #pragma unroll
                for (int mt = 0; mt < 2; mt++) {
                    acc[mt][nt][0] += b0; acc[mt][nt][1] += b1;
                    acc[mt][nt][2] += b0; acc[mt][nt][3] += b1;
                }
            }
        }

        if (master) {
            if (ks == 0) {
                #pragma unroll
                for (int mt = 0; mt < 2; mt++) {
                    int r0 = tile * 32 + mt * 16 + grp;
                    #pragma unroll
                    for (int nt = 0; nt < 4; nt++) {
                        int c0 = nt * 8 + tig * 2;
                        zs[r0 * 33 + c0]           = acc[mt][nt][0];
                        zs[r0 * 33 + c0 + 1]       = acc[mt][nt][1];
                        zs[(r0 + 8) * 33 + c0]     = acc[mt][nt][2];
                        zs[(r0 + 8) * 33 + c0 + 1] = acc[mt][nt][3];
                    }
                }
            }
            __syncthreads();   // (B) zs published
            if (tid < 128) {
                int b = tid >> 1, half = tid & 1;
                const float* lz = zs + b * 33 + half * 16;
                float v[16], mx = -1e30f;
                #pragma unroll
                for (int i = 0; i < 16; i++) { v[i] = lz[i]; mx = fmaxf(mx, v[i]); }
                float s = 0.f;
                #pragma unroll
                for (int i = 0; i < 16; i++) { v[i] = expf(v[i] - mx); s += v[i]; }
                float inv = 1.f / s;
                if (half == 0) {
                    float run = 0.f;
                    #pragma unroll
                    for (int i = 0; i < 16; i++) {
                        run += v[i] * inv;
                        __stcg(&g_masters[b * 32 + i], run);
                    }
                } else {
                    float run = 0.f;
                    #pragma unroll
                    for (int i = 15; i >= 0; i--) {
                        run += v[i] * inv;
                        __stcg(&g_masters[b * 32 + 16 + i], run);
                    }
                }
            }
            __threadfence();
            __syncthreads();   // (C)
            if (tid == 0) *(volatile unsigned*)&g_mflag = (unsigned)(t + 1);
        } else {
            if (ks == 0) {
                // gates directly from register z; cix = mt*4 + e
                float pf[8], pi[8], po[8], pg[8];
                #pragma unroll
                for (int mt = 0; mt < 2; mt++)
                    #pragma unroll
                    for (int e = 0; e < 4; e++) {
                        int cix = mt * 4 + e;
                        pf[cix] = 1.f / (1.f + expf(-acc[mt][0][e]));
                        pi[cix] = 1.f / (1.f + expf(-acc[mt][1][e]));
                        po[cix] = 1.f / (1.f + expf(-acc[mt][2][e]));
                        pg[cix] = tanhf(acc[mt][3][e]);
                    }
                if (lane == 0) {
                    while (*(volatile unsigned*)&g_mflag < (unsigned)(t + 1)) __nanosleep(16);
                }
                __syncwarp();
                uint4* hout4 = g_hq[(t + 1) & 1];
                int j0 = 2 * tig;
                #pragma unroll
                for (int mt = 0; mt < 2; mt++) {
                    int r0 = tile * 32 + mt * 16 + grp;
                    float fm0 = __ldcg(&g_masters[r0 * 32 + lvl]);
                    float im0 = __ldcg(&g_masters[r0 * 32 + 16 + lvl]);
                    float fm1 = __ldcg(&g_masters[(r0 + 8) * 32 + lvl]);
                    float im1 = __ldcg(&g_masters[(r0 + 8) * 32 + 16 + lvl]);
                    float hv[4];
                    #pragma unroll
                    for (int e = 0; e < 4; e++) {
                        int cix = mt * 4 + e;
                        int row = r0 + ((e >> 1) ? 8 : 0);
                        int j   = j0 + (e & 1);
                        float fm = (e >> 1) ? fm1 : fm0;
                        float im = (e >> 1) ? im1 : im0;
                        float cp = cs[row * 8 + j];
                        float w = fm * im;
                        float c = w * (pf[cix] * cp + pi[cix] * pg[cix])
                                + (fm - w) * cp + (im - w) * pg[cix];
                        cs[row * 8 + j] = c;
                        hv[e] = po[cix] * tanhf(c);
                    }
                    float2 o0 = make_float2(hv[0], hv[1]);
                    float2 o1 = make_float2(hv[2], hv[3]);
                    *(float2*)&out[((size_t)r0 * T_ + t) * U_ + u0 + j0] = o0;
                    *(float2*)&out[((size_t)(r0 + 8) * T_ + t) * U_ + u0 + j0] = o1;
                    unsigned w0 = pack2(hv[0], hv[1]);
                    unsigned w1 = pack2(hv[2], hv[3]);
                    char* dst = (char*)(hout4 + (bk >> 1) * 128
                                        + (tile * 2 + mt) * 32 + lane) + (bk & 1) * 8;
                    asm volatile("st.global.cg.v2.u32 [%0], {%1,%2};"
                                 :: "l"(dst), "r"(w0), "r"(w1) : "memory");
                }
                __threadfence();
            }
            __syncthreads();   // (B) h written + red4 consumable
            if (tid == 0) atomicAdd(&g_ctr, 1u);
        }
    }
}

// ---------------- entry -------------------------------------------------------
extern "C" void kernel_launch(void* const* d_in, const int* in_sizes, int n_in,
                              void* d_out, int out_size) {
    const float* x    = (const float*)d_in[0];
    const float* W    = (const float*)d_in[1];
    const float* R    = (const float*)d_in[2];
    const float* bias = (const float*)d_in[3];
    float* out = (float*)d_out;

    // smem: 131072 (Bs) + 24576 (red) + 8448 (zs) + 2048 (cs) + 128 (bs) = 166272
    cudaFuncSetAttribute(k_rec, cudaFuncAttributeMaxDynamicSharedMemorySize, 166272);

    k_pack_aq<<<(int)(((size_t)T_ * 8192 + 255) / 256), 256>>>(x);
    k_pack_bq<<<(NB_ * 8192 + 255) / 256, 256>>>(W, R);
    k_zero<<<32, 256>>>();
    k_rec<<<NB_, 256, 166272>>>(out, bias);
}